// round 3
// baseline (speedup 1.0000x reference)
#include <cuda_runtime.h>
#include <math.h>

#define BS 512
#define NN 256
#define MAXITER 200
#define OMEGA 1.5f
#define NWARP 8
#define RB4 24          // float4 chunks of the row kept in registers (cols 0..95)
#define SB4 40          // float4 chunks of the row kept in smem     (cols 96..255)
// smem floats: ebuf[2][256]=512 | wred[2][8]=16 @512 | ctrl[2] @528 | flags(int[8]) @532 | pad->544
#define MAT_OFF   544
#define SCR_OFF   (MAT_OFF + SB4*NN*4)
#define SMEM_FLOATS (SCR_OFF + NWARP*32*33)

__device__ __forceinline__ void wait_flag(volatile const int* f, int t) {
#pragma unroll 1
    while (*f < t) { }
}

__global__ void __launch_bounds__(NN, 1) sor_fused(
    const float* __restrict__ A, const float* __restrict__ xs,
    const float* __restrict__ theta, const float* __restrict__ rtol,
    float* __restrict__ out)
{
    extern __shared__ float sm[];
    float*  ebuf  = sm;                        // [2][256]
    float*  wred  = sm + 512;                  // [2][8]
    float*  ctrl  = sm + 528;                  // [0]=err0, [1]=xtol
    volatile int* flags = (volatile int*)(sm + 532);   // [8]
    float4* sT4   = (float4*)(sm + MAT_OFF);
    float*  scr   = sm + SCR_OFF;

    const int b = blockIdx.x, tid = threadIdx.x;
    const int wid = tid >> 5, lane = tid & 31;

    // ---------------- load row `tid` of A, scale by omega / a_ii ----------------
    const float*  Ar  = A + ((size_t)b * NN + tid) * NN;
    const float4* Ar4 = (const float4*)Ar;
    const float sc = OMEGA / Ar[tid];
    float4 creg[RB4];
#pragma unroll
    for (int jb = 0; jb < RB4; ++jb) {
        float4 v = Ar4[jb];
        v.x *= sc; v.y *= sc; v.z *= sc; v.w *= sc;
        creg[jb] = v;
    }
#pragma unroll
    for (int jb = 0; jb < SB4; ++jb) {
        float4 v = Ar4[RB4 + jb];
        v.x *= sc; v.y *= sc; v.z *= sc; v.w *= sc;
        sT4[jb * NN + tid] = v;
    }

    // ---------------- e0, err0 = ||e0||, xtol = ||xs||*rtol ---------------------
    const float xv = xs[b * NN + tid];
    float eold = xv - theta[b * NN + tid];
    ebuf[tid] = eold;                          // ebuf[0] = e0
    if (tid < NWARP) flags[tid] = 0;
    {
        float s1 = eold * eold, s2 = xv * xv;
#pragma unroll
        for (int o = 16; o; o >>= 1) {
            s1 += __shfl_xor_sync(0xffffffffu, s1, o);
            s2 += __shfl_xor_sync(0xffffffffu, s2, o);
        }
        if (lane == 0) { wred[wid] = s1; wred[8 + wid] = s2; }
    }
    __syncthreads();
    if (tid == 0) {
        float a1 = 0.f, a2 = 0.f;
#pragma unroll
        for (int w = 0; w < NWARP; ++w) { a1 += wred[w]; a2 += wred[8 + w]; }
        const float err0 = sqrtf(a1);
        out[(size_t)b * (MAXITER + 1)] = err0;
        ctrl[0] = err0;
        ctrl[1] = sqrtf(a2) * rtol[b];
    }

    // ---------------- build M = (I + strict-lower diag-block)^-1 per warp -------
    float* myscr = scr + wid * (32 * 33);
    {
        float seg[32];
        if (wid < 3) {
#pragma unroll
            for (int q = 0; q < 3; ++q) if (wid == q) {
#pragma unroll
                for (int k = 0; k < 8; ++k) {
                    float4 v = creg[q * 8 + k];
                    seg[4*k+0] = v.x; seg[4*k+1] = v.y; seg[4*k+2] = v.z; seg[4*k+3] = v.w;
                }
            }
        } else {
            const int jb0 = wid * 8 - RB4;
#pragma unroll
            for (int k = 0; k < 8; ++k) {
                float4 v = sT4[(jb0 + k) * NN + tid];
                seg[4*k+0] = v.x; seg[4*k+1] = v.y; seg[4*k+2] = v.z; seg[4*k+3] = v.w;
            }
        }
#pragma unroll
        for (int s = 0; s < 32; ++s) myscr[lane * 33 + s] = seg[s];
    }
    __syncwarp();
    {
        float mcol[32];
#pragma unroll
        for (int r = 0; r < 32; ++r) mcol[r] = (r == lane) ? 1.f : 0.f;
#pragma unroll
        for (int r = 1; r < 32; ++r) {
            float s = 0.f;
#pragma unroll
            for (int j = 0; j < r; ++j) s = fmaf(myscr[r * 33 + j], mcol[j], s);
            mcol[r] -= s;
        }
        __syncwarp();
#pragma unroll
        for (int r = 0; r < 32; ++r) myscr[r * 33 + lane] = mcol[r];
    }
    __syncwarp();
    float Mrow[32];
#pragma unroll
    for (int c = 0; c < 32; ++c) Mrow[c] = myscr[lane * 33 + c];

    // ---------------- zero own-block entries j <= tid ---------------------------
    if (wid < 3) {
#pragma unroll
        for (int q = 0; q < 3; ++q) if (wid == q) {
#pragma unroll
            for (int s = 0; s < 32; ++s) {
                const int j = q * 32 + s;
                if (j <= tid) {
                    float4& v = creg[j >> 2];
                    if ((j & 3) == 0) v.x = 0.f;
                    else if ((j & 3) == 1) v.y = 0.f;
                    else if ((j & 3) == 2) v.z = 0.f;
                    else v.w = 0.f;
                }
            }
        }
    } else {
        float* sTf = (float*)sT4;
#pragma unroll
        for (int s = 0; s < 32; ++s) {
            const int j = wid * 32 + s;
            if (j <= tid) {
                const int jb = (j - 96) >> 2;
                sTf[(jb * NN + tid) * 4 + (j & 3)] = 0.f;
            }
        }
    }
    __syncthreads();
    float errp = ctrl[0];
    const float xtol = ctrl[1];

    // ---------------- SOR error iteration: warp dataflow, no block barriers -----
    int t = 1;
    for (; t <= MAXITER; ++t) {
        if (errp <= xtol) break;
        const float4* eo4 = (const float4*)(ebuf + ((t & 1) ^ 1) * NN);  // e_old
        float*        ens = ebuf + (t & 1) * NN;                          // e_new
        const float4* en4 = (const float4*)ens;

        float a0 = 0.f, a1 = 0.f, a2 = 0.f, a3 = 0.f;

        // ---- Phase A: upper blocks q >= wid with e_old (own-lower zeroed) ----
#pragma unroll
        for (int q = 0; q < 3; ++q) if (wid <= q) {
#pragma unroll
            for (int k = 0; k < 8; ++k) {
                const float4 c = creg[q * 8 + k];
                const float4 e = eo4[q * 8 + k];
                a0 = fmaf(c.x, e.x, a0); a1 = fmaf(c.y, e.y, a1);
                a2 = fmaf(c.z, e.z, a2); a3 = fmaf(c.w, e.w, a3);
            }
        }
#pragma unroll
        for (int q = 3; q < 8; ++q) if (wid <= q) {
#pragma unroll
            for (int k = 0; k < 8; ++k) {
                const float4 c = sT4[(q * 8 + k - RB4) * NN + tid];
                const float4 e = eo4[q * 8 + k];
                a0 = fmaf(c.x, e.x, a0); a1 = fmaf(c.y, e.y, a1);
                a2 = fmaf(c.z, e.z, a2); a3 = fmaf(c.w, e.w, a3);
            }
        }

        // ---- Corrections: lower blocks q < wid with e_new (flag-gated) ----
#pragma unroll
        for (int q = 0; q < 3; ++q) if (q < wid) {
            wait_flag(flags + q, t);
            __threadfence_block();
#pragma unroll
            for (int k = 0; k < 8; ++k) {
                const float4 c = creg[q * 8 + k];
                const float4 e = en4[q * 8 + k];
                a0 = fmaf(c.x, e.x, a0); a1 = fmaf(c.y, e.y, a1);
                a2 = fmaf(c.z, e.z, a2); a3 = fmaf(c.w, e.w, a3);
            }
        }
#pragma unroll
        for (int q = 3; q < 7; ++q) if (q < wid) {
            float4 cpre[8];
#pragma unroll
            for (int k = 0; k < 8; ++k)                 // prefetch before spin
                cpre[k] = sT4[(q * 8 + k - RB4) * NN + tid];
            wait_flag(flags + q, t);
            __threadfence_block();
#pragma unroll
            for (int k = 0; k < 8; ++k) {
                const float4 e = en4[q * 8 + k];
                a0 = fmaf(cpre[k].x, e.x, a0); a1 = fmaf(cpre[k].y, e.y, a1);
                a2 = fmaf(cpre[k].z, e.z, a2); a3 = fmaf(cpre[k].w, e.w, a3);
            }
        }

        // ---- Dense 32x32 solve: e_new = M * r ----
        const float r = (1.0f - OMEGA) * eold - ((a0 + a1) + (a2 + a3));
        float e0a = 0.f, e1a = 0.f, e2a = 0.f, e3a = 0.f;
#pragma unroll
        for (int c = 0; c < 32; c += 4) {
            e0a = fmaf(Mrow[c+0], __shfl_sync(0xffffffffu, r, c+0), e0a);
            e1a = fmaf(Mrow[c+1], __shfl_sync(0xffffffffu, r, c+1), e1a);
            e2a = fmaf(Mrow[c+2], __shfl_sync(0xffffffffu, r, c+2), e2a);
            e3a = fmaf(Mrow[c+3], __shfl_sync(0xffffffffu, r, c+3), e3a);
        }
        const float en = (e0a + e1a) + (e2a + e3a);
        ens[tid] = en;

        // partial norm + publish
        float v = en * en;
#pragma unroll
        for (int o = 16; o; o >>= 1) v += __shfl_xor_sync(0xffffffffu, v, o);
        if (lane == 0) wred[(t & 1) * 8 + wid] = v;
        __syncwarp();
        __threadfence_block();
        if (lane == 0) flags[wid] = t;

        // ---- err: wait all blocks of this iteration, sum (identical per warp) --
#pragma unroll
        for (int q = 0; q < NWARP; ++q) wait_flag(flags + q, t);
        __threadfence_block();
        float s = 0.f;
#pragma unroll
        for (int w = 0; w < NWARP; ++w) s += wred[(t & 1) * 8 + w];
        errp = sqrtf(s);
        if (tid == 0) out[(size_t)b * (MAXITER + 1) + t] = errp;
        eold = en;
    }

    // zero-fill remaining history slots
    for (int z = t + tid; z <= MAXITER; z += NN)
        out[(size_t)b * (MAXITER + 1) + z] = 0.f;
}

// ---------------------------------------------------------------------------
extern "C" void kernel_launch(void* const* d_in, const int* in_sizes, int n_in,
                              void* d_out, int out_size) {
    const float* A     = (const float*)d_in[0];
    // d_in[1] = b — not needed (error-vector formulation)
    const float* xs    = (const float*)d_in[2];
    const float* theta = (const float*)d_in[3];
    const float* rtol  = (const float*)d_in[4];
    float* out = (float*)d_out;

    static int smem_set = 0;
    if (!smem_set) {
        cudaFuncSetAttribute(sor_fused, cudaFuncAttributeMaxDynamicSharedMemorySize,
                             SMEM_FLOATS * (int)sizeof(float));
        smem_set = 1;
    }
    sor_fused<<<BS, NN, SMEM_FLOATS * sizeof(float)>>>(A, xs, theta, rtol, out);
}

// round 4
// speedup vs baseline: 1.3702x; 1.3702x over previous
#include <cuda_runtime.h>
#include <math.h>

#define BS 512
#define NN 256
#define MAXITER 200
#define OMEGA 1.5f
#define RB4 24          // float4 chunks in registers (cols 0..95)
#define SB4 40          // float4 chunks in smem     (cols 96..255)

// smem float offsets
#define EBUF  0                       // 2*256
#define WRED  512                     // 8
#define WRED2 520                     // 8
#define RS    528                     // 32 (+pad to 576)
#define MAT   576                     // SB4*NN*4 floats = 40960
#define SCR   (MAT + SB4*NN*4)        // 8 * 1056 = 8448 (group g: B at SCR+2g*1056)
#define SMEM_FLOATS (SCR + 8*1056)    // 49984 floats = 199936 B

__global__ void __launch_bounds__(NN, 1) sor_fused(
    const float* __restrict__ A, const float* __restrict__ xs,
    const float* __restrict__ theta, const float* __restrict__ rtol,
    float* __restrict__ out)
{
    extern __shared__ float sm[];
    float*  ebuf = sm + EBUF;
    float*  wred = sm + WRED;
    float*  wred2= sm + WRED2;
    float*  r_s  = sm + RS;
    float4* sT4  = (float4*)(sm + MAT);
    float*  sTf  = sm + MAT;
    float*  scr  = sm + SCR;

    const int b = blockIdx.x, tid = threadIdx.x;
    const int wid = tid >> 5, lane = tid & 31, g = wid >> 1;

    // ---------------- load row `tid` of A, scale by omega / a_ii ----------------
    const float*  Ar  = A + ((size_t)b * NN + tid) * NN;
    const float4* Ar4 = (const float4*)Ar;
    const float sc = OMEGA / Ar[tid];
    float4 creg[RB4];
#pragma unroll
    for (int jb = 0; jb < RB4; ++jb) {
        float4 v = Ar4[jb];
        v.x *= sc; v.y *= sc; v.z *= sc; v.w *= sc;
        creg[jb] = v;
    }
#pragma unroll
    for (int jb = 0; jb < SB4; ++jb) {
        float4 v = Ar4[RB4 + jb];
        v.x *= sc; v.y *= sc; v.z *= sc; v.w *= sc;
        sT4[jb * NN + tid] = v;
    }

    // ---------------- e0 = xs - theta; partial norms ----------------------------
    const float xv = xs[b * NN + tid];
    float eold = xv - theta[b * NN + tid];
    ebuf[tid] = eold;
    {
        float s1 = eold * eold, s2 = xv * xv;
#pragma unroll
        for (int o = 16; o; o >>= 1) {
            s1 += __shfl_xor_sync(0xffffffffu, s1, o);
            s2 += __shfl_xor_sync(0xffffffffu, s2, o);
        }
        if (lane == 0) { wred[wid] = s1; wred2[wid] = s2; }
    }

    // ---------------- step 1: per-warp 32x32 unit-lower inverse -----------------
    float* myscr = scr + wid * 1056;
    {
        float seg[32];
        if (wid < 3) {
#pragma unroll
            for (int q = 0; q < 3; ++q) if (wid == q) {
#pragma unroll
                for (int k = 0; k < 8; ++k) {
                    float4 v = creg[q * 8 + k];
                    seg[4*k+0] = v.x; seg[4*k+1] = v.y; seg[4*k+2] = v.z; seg[4*k+3] = v.w;
                }
            }
        } else {
            const int jb0 = wid * 8 - RB4;
#pragma unroll
            for (int k = 0; k < 8; ++k) {
                float4 v = sT4[(jb0 + k) * NN + tid];
                seg[4*k+0] = v.x; seg[4*k+1] = v.y; seg[4*k+2] = v.z; seg[4*k+3] = v.w;
            }
        }
#pragma unroll
        for (int s = 0; s < 32; ++s) myscr[lane * 33 + s] = seg[s];
    }
    __syncwarp();
    {
        float mcol[32];
#pragma unroll
        for (int r = 0; r < 32; ++r) mcol[r] = (r == lane) ? 1.f : 0.f;
#pragma unroll
        for (int r = 1; r < 32; ++r) {
            float s = 0.f;
#pragma unroll
            for (int j = 0; j < r; ++j) s = fmaf(myscr[r * 33 + j], mcol[j], s);
            mcol[r] -= s;
        }
        __syncwarp();
#pragma unroll
        for (int r = 0; r < 32; ++r) myscr[r * 33 + lane] = mcol[r];
    }
    __syncwarp();
    float Mrow[32];
#pragma unroll
    for (int c = 0; c < 32; ++c) Mrow[c] = myscr[lane * 33 + c];

    __syncthreads();   // wred/wred2 ready; partner scratch (M11) ready

    // ---------------- err0 / xtol (computed identically by every thread) --------
    float errp, xtol;
    {
        float a1 = 0.f, a2 = 0.f;
#pragma unroll
        for (int w = 0; w < 8; ++w) { a1 += wred[w]; a2 += wred2[w]; }
        errp = sqrtf(a1);
        xtol = sqrtf(a2) * rtol[b];
        if (tid == 0) out[(size_t)b * (MAXITER + 1)] = errp;
    }

    // ---------------- odd warps: B = -M22 * C21 * M11 -> persisted in escr ------
    if (wid & 1) {
        float* escr = scr + (wid - 1) * 1056;   // partner's M11; becomes B
        float* oscr = myscr;                     // own M22 scratch -> reused for X
        float c21[32];
        if (wid == 1) {
#pragma unroll
            for (int k = 0; k < 8; ++k) {
                float4 v = creg[k];
                c21[4*k+0]=v.x; c21[4*k+1]=v.y; c21[4*k+2]=v.z; c21[4*k+3]=v.w;
            }
        } else if (wid == 3) {
#pragma unroll
            for (int k = 0; k < 8; ++k) {
                float4 v = creg[16 + k];
                c21[4*k+0]=v.x; c21[4*k+1]=v.y; c21[4*k+2]=v.z; c21[4*k+3]=v.w;
            }
        } else if (wid == 5) {
#pragma unroll
            for (int k = 0; k < 8; ++k) {
                float4 v = sT4[(8 + k) * NN + tid];
                c21[4*k+0]=v.x; c21[4*k+1]=v.y; c21[4*k+2]=v.z; c21[4*k+3]=v.w;
            }
        } else {
#pragma unroll
            for (int k = 0; k < 8; ++k) {
                float4 v = sT4[(24 + k) * NN + tid];
                c21[4*k+0]=v.x; c21[4*k+1]=v.y; c21[4*k+2]=v.z; c21[4*k+3]=v.w;
            }
        }
        // X = C21 * M11  (row `lane` of X)
#pragma unroll 1
        for (int c = 0; c < 32; ++c) {
            float x = 0.f;
#pragma unroll
            for (int j = 0; j < 32; ++j) x = fmaf(c21[j], escr[j * 33 + c], x);
            oscr[lane * 33 + c] = x;
        }
        __syncwarp();
        // B = -M22 * X  (row `lane`), written over M11
#pragma unroll 1
        for (int c = 0; c < 32; ++c) {
            float y = 0.f;
#pragma unroll
            for (int j = 0; j < 32; ++j) y = fmaf(Mrow[j], oscr[j * 33 + c], y);
            escr[lane * 33 + c] = -y;
        }
    }

    // ---------------- zero own-64-block entries j <= tid ------------------------
    if (wid < 2) {
#pragma unroll
        for (int s = 0; s < 64; ++s) if (s <= tid) {
            float4& v = creg[s >> 2];
            if ((s & 3) == 0) v.x = 0.f; else if ((s & 3) == 1) v.y = 0.f;
            else if ((s & 3) == 2) v.z = 0.f; else v.w = 0.f;
        }
    } else if (wid < 4) {
#pragma unroll
        for (int s = 0; s < 32; ++s) { int j = 64 + s; if (j <= tid) {
            float4& v = creg[16 + (s >> 2)];
            if ((s & 3) == 0) v.x = 0.f; else if ((s & 3) == 1) v.y = 0.f;
            else if ((s & 3) == 2) v.z = 0.f; else v.w = 0.f;
        } }
#pragma unroll
        for (int s = 32; s < 64; ++s) { int j = 64 + s; if (j <= tid)
            sTf[((((s - 32) >> 2)) * NN + tid) * 4 + (s & 3)] = 0.f; }
    } else if (wid < 6) {
#pragma unroll
        for (int s = 0; s < 64; ++s) { int j = 128 + s; if (j <= tid)
            sTf[((8 + (s >> 2)) * NN + tid) * 4 + (s & 3)] = 0.f; }
    } else {
#pragma unroll
        for (int s = 0; s < 64; ++s) { int j = 192 + s; if (j <= tid)
            sTf[((24 + (s >> 2)) * NN + tid) * 4 + (s & 3)] = 0.f; }
    }
    __syncthreads();   // B, e0, zeroed matrix visible

    // ---------------- SOR iteration: 4 stages of 64 -----------------------------
    int t = 1;
    for (; t <= MAXITER; ++t) {
        if (errp <= xtol) break;
        const float4* eo4 = (const float4*)(ebuf + ((t & 1) ^ 1) * NN);
        float*        ens = ebuf + (t & 1) * NN;
        const float4* en4 = (const float4*)ens;

        float a0 = 0.f, a1 = 0.f, a2 = 0.f, a3 = 0.f;
        // ---- Phase A: col-blocks q4 >= g with e_old (own lower zeroed) ----
        if (g == 0) {
#pragma unroll
            for (int c = 0; c < 16; ++c) {
                const float4 cc = creg[c]; const float4 e = eo4[c];
                a0 = fmaf(cc.x, e.x, a0); a1 = fmaf(cc.y, e.y, a1);
                a2 = fmaf(cc.z, e.z, a2); a3 = fmaf(cc.w, e.w, a3);
            }
        }
        if (g <= 1) {
#pragma unroll
            for (int c = 16; c < 24; ++c) {
                const float4 cc = creg[c]; const float4 e = eo4[c];
                a0 = fmaf(cc.x, e.x, a0); a1 = fmaf(cc.y, e.y, a1);
                a2 = fmaf(cc.z, e.z, a2); a3 = fmaf(cc.w, e.w, a3);
            }
#pragma unroll
            for (int c = 24; c < 32; ++c) {
                const float4 cc = sT4[(c - 24) * NN + tid]; const float4 e = eo4[c];
                a0 = fmaf(cc.x, e.x, a0); a1 = fmaf(cc.y, e.y, a1);
                a2 = fmaf(cc.z, e.z, a2); a3 = fmaf(cc.w, e.w, a3);
            }
        }
        if (g <= 2) {
#pragma unroll
            for (int c = 32; c < 48; ++c) {
                const float4 cc = sT4[(c - 24) * NN + tid]; const float4 e = eo4[c];
                a0 = fmaf(cc.x, e.x, a0); a1 = fmaf(cc.y, e.y, a1);
                a2 = fmaf(cc.z, e.z, a2); a3 = fmaf(cc.w, e.w, a3);
            }
        }
#pragma unroll
        for (int c = 48; c < 64; ++c) {
            const float4 cc = sT4[(c - 24) * NN + tid]; const float4 e = eo4[c];
            a0 = fmaf(cc.x, e.x, a0); a1 = fmaf(cc.y, e.y, a1);
            a2 = fmaf(cc.z, e.z, a2); a3 = fmaf(cc.w, e.w, a3);
        }

        float en = 0.f;
#pragma unroll
        for (int p = 0; p < 4; ++p) {
            __syncthreads();
            // corrections from freshly published block p-1 (e_new)
            if (p == 1 && g >= 1) {
#pragma unroll
                for (int c = 0; c < 16; ++c) {
                    const float4 cc = creg[c]; const float4 e = en4[c];
                    a0 = fmaf(cc.x, e.x, a0); a1 = fmaf(cc.y, e.y, a1);
                    a2 = fmaf(cc.z, e.z, a2); a3 = fmaf(cc.w, e.w, a3);
                }
            } else if (p == 2 && g >= 2) {
#pragma unroll
                for (int c = 16; c < 24; ++c) {
                    const float4 cc = creg[c]; const float4 e = en4[c];
                    a0 = fmaf(cc.x, e.x, a0); a1 = fmaf(cc.y, e.y, a1);
                    a2 = fmaf(cc.z, e.z, a2); a3 = fmaf(cc.w, e.w, a3);
                }
#pragma unroll
                for (int c = 24; c < 32; ++c) {
                    const float4 cc = sT4[(c - 24) * NN + tid]; const float4 e = en4[c];
                    a0 = fmaf(cc.x, e.x, a0); a1 = fmaf(cc.y, e.y, a1);
                    a2 = fmaf(cc.z, e.z, a2); a3 = fmaf(cc.w, e.w, a3);
                }
            } else if (p == 3 && g >= 3) {
#pragma unroll
                for (int c = 32; c < 48; ++c) {
                    const float4 cc = sT4[(c - 24) * NN + tid]; const float4 e = en4[c];
                    a0 = fmaf(cc.x, e.x, a0); a1 = fmaf(cc.y, e.y, a1);
                    a2 = fmaf(cc.z, e.z, a2); a3 = fmaf(cc.w, e.w, a3);
                }
            }
            // solve for group p
            if (g == p) {
                const float r = (1.0f - OMEGA) * eold - ((a0 + a1) + (a2 + a3));
                if ((wid & 1) == 0) r_s[lane] = r;
                asm volatile("bar.sync %0, %1;" :: "r"(g + 1), "r"(64) : "memory");
                float e0a = 0.f, e1a = 0.f, e2a = 0.f, e3a = 0.f;
                if ((wid & 1) == 0) {
#pragma unroll
                    for (int k = 0; k < 32; k += 4) {
                        e0a = fmaf(Mrow[k+0], __shfl_sync(0xffffffffu, r, k+0), e0a);
                        e1a = fmaf(Mrow[k+1], __shfl_sync(0xffffffffu, r, k+1), e1a);
                        e2a = fmaf(Mrow[k+2], __shfl_sync(0xffffffffu, r, k+2), e2a);
                        e3a = fmaf(Mrow[k+3], __shfl_sync(0xffffffffu, r, k+3), e3a);
                    }
                } else {
                    const float* Bl = scr + (wid - 1) * 1056 + lane * 33;
#pragma unroll
                    for (int k = 0; k < 32; k += 2) {
                        e0a = fmaf(Bl[k+0], r_s[k+0], e0a);
                        e1a = fmaf(Mrow[k+0], __shfl_sync(0xffffffffu, r, k+0), e1a);
                        e2a = fmaf(Bl[k+1], r_s[k+1], e2a);
                        e3a = fmaf(Mrow[k+1], __shfl_sync(0xffffffffu, r, k+1), e3a);
                    }
                }
                en = (e0a + e1a) + (e2a + e3a);
                ens[tid] = en;
                float v = en * en;
#pragma unroll
                for (int o = 16; o; o >>= 1) v += __shfl_xor_sync(0xffffffffu, v, o);
                if (lane == 0) wred[wid] = v;
            }
        }

        __syncthreads();
        float s = 0.f;
#pragma unroll
        for (int w = 0; w < 8; ++w) s += wred[w];
        errp = sqrtf(s);
        if (tid == 0) out[(size_t)b * (MAXITER + 1) + t] = errp;
        eold = en;
    }

    // zero-fill remaining history slots
    for (int z = t + tid; z <= MAXITER; z += NN)
        out[(size_t)b * (MAXITER + 1) + z] = 0.f;
}

// ---------------------------------------------------------------------------
extern "C" void kernel_launch(void* const* d_in, const int* in_sizes, int n_in,
                              void* d_out, int out_size) {
    const float* A     = (const float*)d_in[0];
    // d_in[1] = b — not needed (error-vector formulation)
    const float* xs    = (const float*)d_in[2];
    const float* theta = (const float*)d_in[3];
    const float* rtol  = (const float*)d_in[4];
    float* out = (float*)d_out;

    static int smem_set = 0;
    if (!smem_set) {
        cudaFuncSetAttribute(sor_fused, cudaFuncAttributeMaxDynamicSharedMemorySize,
                             SMEM_FLOATS * (int)sizeof(float));
        smem_set = 1;
    }
    sor_fused<<<BS, NN, SMEM_FLOATS * sizeof(float)>>>(A, xs, theta, rtol, out);
}

// round 5
// speedup vs baseline: 1.3856x; 1.0112x over previous
#include <cuda_runtime.h>
#include <math.h>

#define BS 512
#define NN 256
#define MAXITER 200
#define OMEGA 1.5f
#define RB4 20          // float4 chunks in registers (cols 0..79)
#define SB4 44          // float4 chunks in smem     (cols 80..255)

// smem float offsets
#define EBUF  0                       // 2*256
#define WRED  512                     // 8
#define WRED2 520                     // 8
#define RS    528                     // 32 (+pad to 576)
#define MAT   576                     // SB4*NN*4 floats = 45056
#define SCR   (MAT + SB4*NN*4)        // 8 * 1056
#define SMEM_FLOATS (SCR + 8*1056)    // 54080 floats = 216320 B

__global__ void __launch_bounds__(NN, 1) sor_fused(
    const float* __restrict__ A, const float* __restrict__ xs,
    const float* __restrict__ theta, const float* __restrict__ rtol,
    float* __restrict__ out)
{
    extern __shared__ float sm[];
    float*  ebuf = sm + EBUF;
    float*  wred = sm + WRED;
    float*  wred2= sm + WRED2;
    float*  r_s  = sm + RS;
    float4* sT4  = (float4*)(sm + MAT);
    float*  sTf  = sm + MAT;
    float*  scr  = sm + SCR;

    const int b = blockIdx.x, tid = threadIdx.x;
    const int wid = tid >> 5, lane = tid & 31, g = wid >> 1;

    // ---------------- load row `tid` of A, scale by omega / a_ii ----------------
    const float*  Ar  = A + ((size_t)b * NN + tid) * NN;
    const float4* Ar4 = (const float4*)Ar;
    const float sc = OMEGA / Ar[tid];
    float4 creg[RB4];
#pragma unroll
    for (int jb = 0; jb < RB4; ++jb) {
        float4 v = Ar4[jb];
        v.x *= sc; v.y *= sc; v.z *= sc; v.w *= sc;
        creg[jb] = v;
    }
#pragma unroll 4
    for (int jb = 0; jb < SB4; ++jb) {
        float4 v = Ar4[RB4 + jb];
        v.x *= sc; v.y *= sc; v.z *= sc; v.w *= sc;
        sT4[jb * NN + tid] = v;
    }

    // ---------------- e0 = xs - theta; partial norms ----------------------------
    const float xv = xs[b * NN + tid];
    float eold = xv - theta[b * NN + tid];
    ebuf[tid] = eold;
    {
        float s1 = eold * eold, s2 = xv * xv;
#pragma unroll
        for (int o = 16; o; o >>= 1) {
            s1 += __shfl_xor_sync(0xffffffffu, s1, o);
            s2 += __shfl_xor_sync(0xffffffffu, s2, o);
        }
        if (lane == 0) { wred[wid] = s1; wred2[wid] = s2; }
    }

    // ---------------- step 1: per-warp 32x32 unit-lower diag block -> scratch ---
    // warp w owns rows 32w..32w+31; its diag block = chunks 8w..8w+7
    float* myscr = scr + wid * 1056;
    if (wid == 0) {
#pragma unroll
        for (int k = 0; k < 8; ++k) {
            const float4 v = creg[k];
            myscr[lane*33+4*k+0]=v.x; myscr[lane*33+4*k+1]=v.y;
            myscr[lane*33+4*k+2]=v.z; myscr[lane*33+4*k+3]=v.w;
        }
    } else if (wid == 1) {
#pragma unroll
        for (int k = 0; k < 8; ++k) {
            const float4 v = creg[8 + k];
            myscr[lane*33+4*k+0]=v.x; myscr[lane*33+4*k+1]=v.y;
            myscr[lane*33+4*k+2]=v.z; myscr[lane*33+4*k+3]=v.w;
        }
    } else if (wid == 2) {
#pragma unroll
        for (int k = 0; k < 4; ++k) {
            const float4 v = creg[16 + k];
            myscr[lane*33+4*k+0]=v.x; myscr[lane*33+4*k+1]=v.y;
            myscr[lane*33+4*k+2]=v.z; myscr[lane*33+4*k+3]=v.w;
        }
#pragma unroll
        for (int k = 4; k < 8; ++k) {
            const float4 v = sT4[(k - 4) * NN + tid];
            myscr[lane*33+4*k+0]=v.x; myscr[lane*33+4*k+1]=v.y;
            myscr[lane*33+4*k+2]=v.z; myscr[lane*33+4*k+3]=v.w;
        }
    } else {
        const int jb0 = wid * 8 - RB4;
#pragma unroll
        for (int k = 0; k < 8; ++k) {
            const float4 v = sT4[(jb0 + k) * NN + tid];
            myscr[lane*33+4*k+0]=v.x; myscr[lane*33+4*k+1]=v.y;
            myscr[lane*33+4*k+2]=v.z; myscr[lane*33+4*k+3]=v.w;
        }
    }
    __syncwarp();
    // invert unit-lower 32x32: lane c builds column c
    {
        float mcol[32];
#pragma unroll
        for (int r = 0; r < 32; ++r) mcol[r] = (r == lane) ? 1.f : 0.f;
#pragma unroll
        for (int r = 1; r < 32; ++r) {
            float s = 0.f;
#pragma unroll
            for (int j = 0; j < r; ++j) s = fmaf(myscr[r * 33 + j], mcol[j], s);
            mcol[r] -= s;
        }
        __syncwarp();
#pragma unroll
        for (int r = 0; r < 32; ++r) myscr[r * 33 + lane] = mcol[r];
    }
    __syncwarp();
    float Mrow[32];
#pragma unroll
    for (int c = 0; c < 32; ++c) Mrow[c] = myscr[lane * 33 + c];

    __syncthreads();   // wred/wred2 ready; partner scratch (M11) ready

    // ---------------- err0 / xtol (identical in every thread) -------------------
    float errp, xtol;
    {
        float a1 = 0.f, a2 = 0.f;
#pragma unroll
        for (int w = 0; w < 8; ++w) { a1 += wred[w]; a2 += wred2[w]; }
        errp = sqrtf(a1);
        xtol = sqrtf(a2) * rtol[b];
        if (tid == 0) out[(size_t)b * (MAXITER + 1)] = errp;
    }

    // ---------------- odd warps: B = -M22 * (C21 * M11) -> overwrite M11 slot ---
    if (wid & 1) {
        float* escr = scr + (wid - 1) * 1056;   // partner M11 -> becomes B
        float* oscr = myscr;                     // own scratch reused for X
        float c21[32];
        if (wid == 1) {
#pragma unroll
            for (int k = 0; k < 8; ++k) {
                const float4 v = creg[k];
                c21[4*k+0]=v.x; c21[4*k+1]=v.y; c21[4*k+2]=v.z; c21[4*k+3]=v.w;
            }
        } else if (wid == 3) {
#pragma unroll
            for (int k = 0; k < 4; ++k) {
                const float4 v = creg[16 + k];
                c21[4*k+0]=v.x; c21[4*k+1]=v.y; c21[4*k+2]=v.z; c21[4*k+3]=v.w;
            }
#pragma unroll
            for (int k = 4; k < 8; ++k) {
                const float4 v = sT4[(k - 4) * NN + tid];
                c21[4*k+0]=v.x; c21[4*k+1]=v.y; c21[4*k+2]=v.z; c21[4*k+3]=v.w;
            }
        } else if (wid == 5) {
#pragma unroll
            for (int k = 0; k < 8; ++k) {
                const float4 v = sT4[(12 + k) * NN + tid];
                c21[4*k+0]=v.x; c21[4*k+1]=v.y; c21[4*k+2]=v.z; c21[4*k+3]=v.w;
            }
        } else {
#pragma unroll
            for (int k = 0; k < 8; ++k) {
                const float4 v = sT4[(28 + k) * NN + tid];
                c21[4*k+0]=v.x; c21[4*k+1]=v.y; c21[4*k+2]=v.z; c21[4*k+3]=v.w;
            }
        }
        // X = C21 * M11  (row `lane` of X)
#pragma unroll 1
        for (int c = 0; c < 32; ++c) {
            float x = 0.f;
#pragma unroll
            for (int j = 0; j < 32; ++j) x = fmaf(c21[j], escr[j * 33 + c], x);
            oscr[lane * 33 + c] = x;
        }
        __syncwarp();
        // B = -M22 * X  (row `lane`), overwrite M11
#pragma unroll 1
        for (int c = 0; c < 32; ++c) {
            float y = 0.f;
#pragma unroll
            for (int j = 0; j < 32; ++j) y = fmaf(Mrow[j], oscr[j * 33 + c], y);
            escr[lane * 33 + c] = -y;
        }
    }

    // ---------------- zero own-64-block entries j <= tid ------------------------
    if (g == 0) {
#pragma unroll
        for (int s = 0; s < 64; ++s) if (s <= tid) {
            float4& v = creg[s >> 2];
            if ((s & 3) == 0) v.x = 0.f; else if ((s & 3) == 1) v.y = 0.f;
            else if ((s & 3) == 2) v.z = 0.f; else v.w = 0.f;
        }
    } else if (g == 1) {
#pragma unroll
        for (int s = 0; s < 16; ++s) { const int j = 64 + s; if (j <= tid) {
            float4& v = creg[16 + (s >> 2)];
            if ((s & 3) == 0) v.x = 0.f; else if ((s & 3) == 1) v.y = 0.f;
            else if ((s & 3) == 2) v.z = 0.f; else v.w = 0.f;
        } }
#pragma unroll
        for (int s = 16; s < 64; ++s) { const int j = 64 + s; if (j <= tid)
            sTf[((((s - 16) >> 2)) * NN + tid) * 4 + (s & 3)] = 0.f; }
    } else if (g == 2) {
#pragma unroll
        for (int s = 0; s < 64; ++s) { const int j = 128 + s; if (j <= tid)
            sTf[((12 + (s >> 2)) * NN + tid) * 4 + (s & 3)] = 0.f; }
    } else {
#pragma unroll
        for (int s = 0; s < 64; ++s) { const int j = 192 + s; if (j <= tid)
            sTf[((28 + (s >> 2)) * NN + tid) * 4 + (s & 3)] = 0.f; }
    }
    __syncthreads();   // B, e0, zeroed matrix visible

    // ---------------- SOR iteration: 4 stages of 64 -----------------------------
    int t = 1;
    for (; t <= MAXITER; ++t) {
        if (errp <= xtol) break;
        const float4* eo4 = (const float4*)(ebuf + ((t & 1) ^ 1) * NN);
        float*        ens = ebuf + (t & 1) * NN;
        const float4* en4 = (const float4*)ens;

        float a0 = 0.f, a1 = 0.f, a2 = 0.f, a3 = 0.f;
        // ---- Phase A: col groups q >= g with e_old (own lower zeroed) ----
        if (g == 0) {
#pragma unroll
            for (int c = 0; c < 16; ++c) {
                const float4 cc = creg[c]; const float4 e = eo4[c];
                a0 = fmaf(cc.x, e.x, a0); a1 = fmaf(cc.y, e.y, a1);
                a2 = fmaf(cc.z, e.z, a2); a3 = fmaf(cc.w, e.w, a3);
            }
        }
        if (g <= 1) {
#pragma unroll
            for (int c = 16; c < 20; ++c) {
                const float4 cc = creg[c]; const float4 e = eo4[c];
                a0 = fmaf(cc.x, e.x, a0); a1 = fmaf(cc.y, e.y, a1);
                a2 = fmaf(cc.z, e.z, a2); a3 = fmaf(cc.w, e.w, a3);
            }
#pragma unroll
            for (int c = 20; c < 32; ++c) {
                const float4 cc = sT4[(c - 20) * NN + tid]; const float4 e = eo4[c];
                a0 = fmaf(cc.x, e.x, a0); a1 = fmaf(cc.y, e.y, a1);
                a2 = fmaf(cc.z, e.z, a2); a3 = fmaf(cc.w, e.w, a3);
            }
        }
        if (g <= 2) {
#pragma unroll
            for (int c = 32; c < 48; ++c) {
                const float4 cc = sT4[(c - 20) * NN + tid]; const float4 e = eo4[c];
                a0 = fmaf(cc.x, e.x, a0); a1 = fmaf(cc.y, e.y, a1);
                a2 = fmaf(cc.z, e.z, a2); a3 = fmaf(cc.w, e.w, a3);
            }
        }
#pragma unroll
        for (int c = 48; c < 64; ++c) {
            const float4 cc = sT4[(c - 20) * NN + tid]; const float4 e = eo4[c];
            a0 = fmaf(cc.x, e.x, a0); a1 = fmaf(cc.y, e.y, a1);
            a2 = fmaf(cc.z, e.z, a2); a3 = fmaf(cc.w, e.w, a3);
        }

        float en = 0.f;
#pragma unroll
        for (int p = 0; p < 4; ++p) {
            __syncthreads();
            // corrections from freshly published block p-1 (e_new)
            if (p == 1 && g >= 1) {
#pragma unroll
                for (int c = 0; c < 16; ++c) {
                    const float4 cc = creg[c]; const float4 e = en4[c];
                    a0 = fmaf(cc.x, e.x, a0); a1 = fmaf(cc.y, e.y, a1);
                    a2 = fmaf(cc.z, e.z, a2); a3 = fmaf(cc.w, e.w, a3);
                }
            } else if (p == 2 && g >= 2) {
#pragma unroll
                for (int c = 16; c < 20; ++c) {
                    const float4 cc = creg[c]; const float4 e = en4[c];
                    a0 = fmaf(cc.x, e.x, a0); a1 = fmaf(cc.y, e.y, a1);
                    a2 = fmaf(cc.z, e.z, a2); a3 = fmaf(cc.w, e.w, a3);
                }
#pragma unroll
                for (int c = 20; c < 32; ++c) {
                    const float4 cc = sT4[(c - 20) * NN + tid]; const float4 e = en4[c];
                    a0 = fmaf(cc.x, e.x, a0); a1 = fmaf(cc.y, e.y, a1);
                    a2 = fmaf(cc.z, e.z, a2); a3 = fmaf(cc.w, e.w, a3);
                }
            } else if (p == 3 && g >= 3) {
#pragma unroll
                for (int c = 32; c < 48; ++c) {
                    const float4 cc = sT4[(c - 20) * NN + tid]; const float4 e = en4[c];
                    a0 = fmaf(cc.x, e.x, a0); a1 = fmaf(cc.y, e.y, a1);
                    a2 = fmaf(cc.z, e.z, a2); a3 = fmaf(cc.w, e.w, a3);
                }
            }
            // solve for group p
            if (g == p) {
                const float r = (1.0f - OMEGA) * eold - ((a0 + a1) + (a2 + a3));
                if ((wid & 1) == 0) r_s[lane] = r;
                asm volatile("bar.sync %0, %1;" :: "r"(g + 1), "r"(64) : "memory");
                float e0a = 0.f, e1a = 0.f, e2a = 0.f, e3a = 0.f;
                if ((wid & 1) == 0) {
#pragma unroll
                    for (int k = 0; k < 32; k += 4) {
                        e0a = fmaf(Mrow[k+0], __shfl_sync(0xffffffffu, r, k+0), e0a);
                        e1a = fmaf(Mrow[k+1], __shfl_sync(0xffffffffu, r, k+1), e1a);
                        e2a = fmaf(Mrow[k+2], __shfl_sync(0xffffffffu, r, k+2), e2a);
                        e3a = fmaf(Mrow[k+3], __shfl_sync(0xffffffffu, r, k+3), e3a);
                    }
                } else {
                    const float* Bl = scr + (wid - 1) * 1056 + lane * 33;
#pragma unroll
                    for (int k = 0; k < 32; k += 2) {
                        e0a = fmaf(Bl[k+0], r_s[k+0], e0a);
                        e1a = fmaf(Mrow[k+0], __shfl_sync(0xffffffffu, r, k+0), e1a);
                        e2a = fmaf(Bl[k+1], r_s[k+1], e2a);
                        e3a = fmaf(Mrow[k+1], __shfl_sync(0xffffffffu, r, k+1), e3a);
                    }
                }
                en = (e0a + e1a) + (e2a + e3a);
                ens[tid] = en;
                float v = en * en;
#pragma unroll
                for (int o = 16; o; o >>= 1) v += __shfl_xor_sync(0xffffffffu, v, o);
                if (lane == 0) wred[wid] = v;
            }
        }

        __syncthreads();
        float s = 0.f;
#pragma unroll
        for (int w = 0; w < 8; ++w) s += wred[w];
        errp = sqrtf(s);
        if (tid == 0) out[(size_t)b * (MAXITER + 1) + t] = errp;
        eold = en;
    }

    // zero-fill remaining history slots
    for (int z = t + tid; z <= MAXITER; z += NN)
        out[(size_t)b * (MAXITER + 1) + z] = 0.f;
}

// ---------------------------------------------------------------------------
extern "C" void kernel_launch(void* const* d_in, const int* in_sizes, int n_in,
                              void* d_out, int out_size) {
    const float* A     = (const float*)d_in[0];
    // d_in[1] = b — not needed (error-vector formulation)
    const float* xs    = (const float*)d_in[2];
    const float* theta = (const float*)d_in[3];
    const float* rtol  = (const float*)d_in[4];
    float* out = (float*)d_out;

    static int smem_set = 0;
    if (!smem_set) {
        cudaFuncSetAttribute(sor_fused, cudaFuncAttributeMaxDynamicSharedMemorySize,
                             SMEM_FLOATS * (int)sizeof(float));
        smem_set = 1;
    }
    sor_fused<<<BS, NN, SMEM_FLOATS * sizeof(float)>>>(A, xs, theta, rtol, out);
}

// round 6
// speedup vs baseline: 1.4868x; 1.0730x over previous
#include <cuda_runtime.h>
#include <math.h>

#define BS 512
#define NN 256
#define MAXITER 200
#define OMEGA 1.5f
#define RB4 20          // float4 chunks in registers (cols 0..79)
#define SB4 44          // float4 chunks in smem     (cols 80..255)

// smem float offsets
#define EBUF  0                       // 256 (single live e buffer)
#define WRED  256                     // 16 (2 banks x 8)
#define WRED2 272                     // 8
#define RS    288                     // 32 (+pad to 320)
#define MAT   320                     // SB4*NN*4 = 45056 floats
#define SCR   (MAT + SB4*NN*4)        // 8 * 1056
#define SMEM_FLOATS (SCR + 8*1056)    // 53824 floats = 215296 B

// consume newly-published 64-col block B into acc (acc -= C[:,B]·e[B])
template<int B>
__device__ __forceinline__ void consume_blk(float& acc, const float4* __restrict__ creg,
        const float4* __restrict__ sT4, const float4* __restrict__ eb4, int tid)
{
    float a0 = 0.f, a1 = 0.f, a2 = 0.f, a3 = 0.f;
#pragma unroll
    for (int k = 0; k < 16; ++k) {
        const int ch = 16 * B + k;
        float4 c;
        if (ch < RB4) c = creg[ch]; else c = sT4[(ch - RB4) * NN + tid];
        const float4 e = eb4[ch];
        a0 = fmaf(c.x, e.x, a0); a1 = fmaf(c.y, e.y, a1);
        a2 = fmaf(c.z, e.z, a2); a3 = fmaf(c.w, e.w, a3);
    }
    acc -= (a0 + a1) + (a2 + a3);
}

// dense 64x64 unit-lower solve for group P: e_new = Minv * acc; publish; reinit acc
template<int P>
__device__ __forceinline__ void solve_blk(float& acc, float& en, float& normv,
        const float* __restrict__ Mrow, const float* __restrict__ scr,
        float* __restrict__ r_s, float* __restrict__ ebuf, int wid, int lane, int tid)
{
    const float r = acc;
    if ((wid & 1) == 0) r_s[lane] = r;
    asm volatile("bar.sync %0, %1;" :: "r"(P + 1), "r"(64) : "memory");
    float e0a = 0.f, e1a = 0.f, e2a = 0.f, e3a = 0.f;
    if ((wid & 1) == 0) {
#pragma unroll
        for (int k = 0; k < 32; k += 4) {
            e0a = fmaf(Mrow[k+0], __shfl_sync(0xffffffffu, r, k+0), e0a);
            e1a = fmaf(Mrow[k+1], __shfl_sync(0xffffffffu, r, k+1), e1a);
            e2a = fmaf(Mrow[k+2], __shfl_sync(0xffffffffu, r, k+2), e2a);
            e3a = fmaf(Mrow[k+3], __shfl_sync(0xffffffffu, r, k+3), e3a);
        }
    } else {
        const float* Bl = scr + (wid - 1) * 1056 + lane * 33;
#pragma unroll
        for (int k = 0; k < 32; k += 2) {
            e0a = fmaf(Bl[k+0], r_s[k+0], e0a);
            e1a = fmaf(Mrow[k+0], __shfl_sync(0xffffffffu, r, k+0), e1a);
            e2a = fmaf(Bl[k+1], r_s[k+1], e2a);
            e3a = fmaf(Mrow[k+1], __shfl_sync(0xffffffffu, r, k+1), e3a);
        }
    }
    en = (e0a + e1a) + (e2a + e3a);
    ebuf[tid] = en;                    // publish own row
    acc = (1.0f - OMEGA) * en;         // start accumulator for next iteration
    normv = en * en;                   // norm partial (reduced later, off-path)
}

__device__ __forceinline__ void norm_pub(float normv, float* __restrict__ wred,
                                         int bank, int wid, int lane)
{
    float v = normv;
#pragma unroll
    for (int o = 16; o; o >>= 1) v += __shfl_xor_sync(0xffffffffu, v, o);
    if (lane == 0) wred[bank * 8 + wid] = v;
}

__global__ void __launch_bounds__(NN, 1) sor_fused(
    const float* __restrict__ A, const float* __restrict__ xs,
    const float* __restrict__ theta, const float* __restrict__ rtol,
    float* __restrict__ out)
{
    extern __shared__ float sm[];
    float*  ebuf = sm + EBUF;
    float*  wred = sm + WRED;
    float*  wred2= sm + WRED2;
    float*  r_s  = sm + RS;
    float4* sT4  = (float4*)(sm + MAT);
    float*  sTf  = sm + MAT;
    float*  scr  = sm + SCR;
    const float4* eb4 = (const float4*)ebuf;

    const int b = blockIdx.x, tid = threadIdx.x;
    const int wid = tid >> 5, lane = tid & 31, g = wid >> 1;
    const size_t obase = (size_t)b * (MAXITER + 1);

    // ---------------- load row `tid` of A, scale by omega / a_ii ----------------
    const float*  Ar  = A + ((size_t)b * NN + tid) * NN;
    const float4* Ar4 = (const float4*)Ar;
    const float sc = OMEGA / Ar[tid];
    float4 creg[RB4];
#pragma unroll
    for (int jb = 0; jb < RB4; ++jb) {
        float4 v = Ar4[jb];
        v.x *= sc; v.y *= sc; v.z *= sc; v.w *= sc;
        creg[jb] = v;
    }
#pragma unroll 4
    for (int jb = 0; jb < SB4; ++jb) {
        float4 v = Ar4[RB4 + jb];
        v.x *= sc; v.y *= sc; v.z *= sc; v.w *= sc;
        sT4[jb * NN + tid] = v;
    }

    // ---------------- e0 = xs - theta; partial norms ----------------------------
    const float xv = xs[b * NN + tid];
    const float e0v = xv - theta[b * NN + tid];
    ebuf[tid] = e0v;
    {
        float s1 = e0v * e0v, s2 = xv * xv;
#pragma unroll
        for (int o = 16; o; o >>= 1) {
            s1 += __shfl_xor_sync(0xffffffffu, s1, o);
            s2 += __shfl_xor_sync(0xffffffffu, s2, o);
        }
        if (lane == 0) { wred[wid] = s1; wred2[wid] = s2; }
    }

    // ---------------- per-warp 32x32 unit-lower diag block -> scratch -----------
    float* myscr = scr + wid * 1056;
    if (wid == 0) {
#pragma unroll
        for (int k = 0; k < 8; ++k) {
            const float4 v = creg[k];
            myscr[lane*33+4*k+0]=v.x; myscr[lane*33+4*k+1]=v.y;
            myscr[lane*33+4*k+2]=v.z; myscr[lane*33+4*k+3]=v.w;
        }
    } else if (wid == 1) {
#pragma unroll
        for (int k = 0; k < 8; ++k) {
            const float4 v = creg[8 + k];
            myscr[lane*33+4*k+0]=v.x; myscr[lane*33+4*k+1]=v.y;
            myscr[lane*33+4*k+2]=v.z; myscr[lane*33+4*k+3]=v.w;
        }
    } else if (wid == 2) {
#pragma unroll
        for (int k = 0; k < 4; ++k) {
            const float4 v = creg[16 + k];
            myscr[lane*33+4*k+0]=v.x; myscr[lane*33+4*k+1]=v.y;
            myscr[lane*33+4*k+2]=v.z; myscr[lane*33+4*k+3]=v.w;
        }
#pragma unroll
        for (int k = 4; k < 8; ++k) {
            const float4 v = sT4[(k - 4) * NN + tid];
            myscr[lane*33+4*k+0]=v.x; myscr[lane*33+4*k+1]=v.y;
            myscr[lane*33+4*k+2]=v.z; myscr[lane*33+4*k+3]=v.w;
        }
    } else {
        const int jb0 = wid * 8 - RB4;
#pragma unroll
        for (int k = 0; k < 8; ++k) {
            const float4 v = sT4[(jb0 + k) * NN + tid];
            myscr[lane*33+4*k+0]=v.x; myscr[lane*33+4*k+1]=v.y;
            myscr[lane*33+4*k+2]=v.z; myscr[lane*33+4*k+3]=v.w;
        }
    }
    __syncwarp();
    {   // invert unit-lower 32x32: lane c builds column c
        float mcol[32];
#pragma unroll
        for (int r = 0; r < 32; ++r) mcol[r] = (r == lane) ? 1.f : 0.f;
#pragma unroll
        for (int r = 1; r < 32; ++r) {
            float s = 0.f;
#pragma unroll
            for (int j = 0; j < r; ++j) s = fmaf(myscr[r * 33 + j], mcol[j], s);
            mcol[r] -= s;
        }
        __syncwarp();
#pragma unroll
        for (int r = 0; r < 32; ++r) myscr[r * 33 + lane] = mcol[r];
    }
    __syncwarp();
    float Mrow[32];
#pragma unroll
    for (int c = 0; c < 32; ++c) Mrow[c] = myscr[lane * 33 + c];

    __syncthreads();   // wred/wred2 ready; partner scratch (M11) ready

    // ---------------- err0 / xtol (identical in every thread) -------------------
    float errp, xtol;
    {
        float a1 = 0.f, a2 = 0.f;
#pragma unroll
        for (int w = 0; w < 8; ++w) { a1 += wred[w]; a2 += wred2[w]; }
        errp = sqrtf(a1);
        xtol = sqrtf(a2) * rtol[b];
        if (tid == 0) out[obase] = errp;
    }

    // ---------------- odd warps: B = -M22 * (C21 * M11) -> overwrite M11 slot ---
    if (wid & 1) {
        float* escr = scr + (wid - 1) * 1056;
        float* oscr = myscr;
        float c21[32];
        if (wid == 1) {
#pragma unroll
            for (int k = 0; k < 8; ++k) {
                const float4 v = creg[k];
                c21[4*k+0]=v.x; c21[4*k+1]=v.y; c21[4*k+2]=v.z; c21[4*k+3]=v.w;
            }
        } else if (wid == 3) {
#pragma unroll
            for (int k = 0; k < 4; ++k) {
                const float4 v = creg[16 + k];
                c21[4*k+0]=v.x; c21[4*k+1]=v.y; c21[4*k+2]=v.z; c21[4*k+3]=v.w;
            }
#pragma unroll
            for (int k = 4; k < 8; ++k) {
                const float4 v = sT4[(k - 4) * NN + tid];
                c21[4*k+0]=v.x; c21[4*k+1]=v.y; c21[4*k+2]=v.z; c21[4*k+3]=v.w;
            }
        } else if (wid == 5) {
#pragma unroll
            for (int k = 0; k < 8; ++k) {
                const float4 v = sT4[(12 + k) * NN + tid];
                c21[4*k+0]=v.x; c21[4*k+1]=v.y; c21[4*k+2]=v.z; c21[4*k+3]=v.w;
            }
        } else {
#pragma unroll
            for (int k = 0; k < 8; ++k) {
                const float4 v = sT4[(28 + k) * NN + tid];
                c21[4*k+0]=v.x; c21[4*k+1]=v.y; c21[4*k+2]=v.z; c21[4*k+3]=v.w;
            }
        }
#pragma unroll 1
        for (int c = 0; c < 32; ++c) {   // X = C21 * M11
            float x = 0.f;
#pragma unroll
            for (int j = 0; j < 32; ++j) x = fmaf(c21[j], escr[j * 33 + c], x);
            oscr[lane * 33 + c] = x;
        }
        __syncwarp();
#pragma unroll 1
        for (int c = 0; c < 32; ++c) {   // B = -M22 * X, overwrite M11
            float y = 0.f;
#pragma unroll
            for (int j = 0; j < 32; ++j) y = fmaf(Mrow[j], oscr[j * 33 + c], y);
            escr[lane * 33 + c] = -y;
        }
    }

    // ---------------- zero own-64-block entries j <= tid ------------------------
    if (g == 0) {
#pragma unroll
        for (int s = 0; s < 64; ++s) if (s <= tid) {
            float4& v = creg[s >> 2];
            if ((s & 3) == 0) v.x = 0.f; else if ((s & 3) == 1) v.y = 0.f;
            else if ((s & 3) == 2) v.z = 0.f; else v.w = 0.f;
        }
    } else if (g == 1) {
#pragma unroll
        for (int s = 0; s < 16; ++s) { const int j = 64 + s; if (j <= tid) {
            float4& v = creg[16 + (s >> 2)];
            if ((s & 3) == 0) v.x = 0.f; else if ((s & 3) == 1) v.y = 0.f;
            else if ((s & 3) == 2) v.z = 0.f; else v.w = 0.f;
        } }
#pragma unroll
        for (int s = 16; s < 64; ++s) { const int j = 64 + s; if (j <= tid)
            sTf[((((s - 16) >> 2)) * NN + tid) * 4 + (s & 3)] = 0.f; }
    } else if (g == 2) {
#pragma unroll
        for (int s = 0; s < 64; ++s) { const int j = 128 + s; if (j <= tid)
            sTf[((12 + (s >> 2)) * NN + tid) * 4 + (s & 3)] = 0.f; }
    } else {
#pragma unroll
        for (int s = 0; s < 64; ++s) { const int j = 192 + s; if (j <= tid)
            sTf[((28 + (s >> 2)) * NN + tid) * 4 + (s & 3)] = 0.f; }
    }
    __syncthreads();   // B, e0, zeroed matrix visible

    // ---------------- prologue: acc for iter 1 from e0 (blocks >= g) ------------
    float acc = (1.0f - OMEGA) * e0v;
    if (g == 0) {
        consume_blk<0>(acc, creg, sT4, eb4, tid);
        consume_blk<1>(acc, creg, sT4, eb4, tid);
        consume_blk<2>(acc, creg, sT4, eb4, tid);
        consume_blk<3>(acc, creg, sT4, eb4, tid);
    } else if (g == 1) {
        consume_blk<1>(acc, creg, sT4, eb4, tid);
        consume_blk<2>(acc, creg, sT4, eb4, tid);
        consume_blk<3>(acc, creg, sT4, eb4, tid);
    } else if (g == 2) {
        consume_blk<2>(acc, creg, sT4, eb4, tid);
        consume_blk<3>(acc, creg, sT4, eb4, tid);
    } else {
        consume_blk<3>(acc, creg, sT4, eb4, tid);
    }

    // ---------------- pipelined mainloop ----------------------------------------
    float en = 0.f, normv = 0.f;
    int t = 1;
    for (; t <= MAXITER; ++t) {
        // ======== stage 0 ========
        __syncthreads();                       // block 3 of iter t-1 published
        if (t > 1) {
            float s = 0.f;
#pragma unroll
            for (int w = 0; w < 8; ++w) s += wred[(((t - 1) & 1)) * 8 + w];
            errp = sqrtf(s);
            if (tid == 0) out[obase + (t - 1)] = errp;
        }
        if (errp <= xtol) break;
        if (t > 1) consume_blk<3>(acc, creg, sT4, eb4, tid);
        if (g == 0) solve_blk<0>(acc, en, normv, Mrow, scr, r_s, ebuf, wid, lane, tid);

        // ======== stage 1 ========
        __syncthreads();                       // block 0 of iter t published
        consume_blk<0>(acc, creg, sT4, eb4, tid);
        if (g == 0) norm_pub(normv, wred, t & 1, wid, lane);          // deferred
        if (g == 1) solve_blk<1>(acc, en, normv, Mrow, scr, r_s, ebuf, wid, lane, tid);

        // ======== stage 2 ========
        __syncthreads();                       // block 1 published
        consume_blk<1>(acc, creg, sT4, eb4, tid);
        if (g == 1) norm_pub(normv, wred, t & 1, wid, lane);          // deferred
        if (g == 2) solve_blk<2>(acc, en, normv, Mrow, scr, r_s, ebuf, wid, lane, tid);

        // ======== stage 3 ========
        __syncthreads();                       // block 2 published
        consume_blk<2>(acc, creg, sT4, eb4, tid);
        if (g == 2) norm_pub(normv, wred, t & 1, wid, lane);          // deferred
        if (g == 3) {
            solve_blk<3>(acc, en, normv, Mrow, scr, r_s, ebuf, wid, lane, tid);
            norm_pub(normv, wred, t & 1, wid, lane);                  // inline (last)
        }
    }

    // ---------------- epilogue ---------------------------------------------------
    int zf;
    if (t > MAXITER) {     // natural exit: err_MAXITER still unwritten
        __syncthreads();
        float s = 0.f;
#pragma unroll
        for (int w = 0; w < 8; ++w) s += wred[((MAXITER & 1)) * 8 + w];
        if (tid == 0) out[obase + MAXITER] = sqrtf(s);
        zf = MAXITER + 1;
    } else {
        zf = t;            // broke at pass t: out[t-1] written, zero t..MAXITER
    }
    for (int z = zf + tid; z <= MAXITER; z += NN)
        out[obase + z] = 0.f;
}

// ---------------------------------------------------------------------------
extern "C" void kernel_launch(void* const* d_in, const int* in_sizes, int n_in,
                              void* d_out, int out_size) {
    const float* A     = (const float*)d_in[0];
    // d_in[1] = b — not needed (error-vector formulation)
    const float* xs    = (const float*)d_in[2];
    const float* theta = (const float*)d_in[3];
    const float* rtol  = (const float*)d_in[4];
    float* out = (float*)d_out;

    static int smem_set = 0;
    if (!smem_set) {
        cudaFuncSetAttribute(sor_fused, cudaFuncAttributeMaxDynamicSharedMemorySize,
                             SMEM_FLOATS * (int)sizeof(float));
        smem_set = 1;
    }
    sor_fused<<<BS, NN, SMEM_FLOATS * sizeof(float)>>>(A, xs, theta, rtol, out);
}